// round 14
// baseline (speedup 1.0000x reference)
#include <cuda_runtime.h>
#include <cuda_bf16.h>
#include <cstdint>

#define B_ 8
#define N_ 1024
#define E_ 128
#define T_ 16
#define M_ 256
#define KS_ 8
#define MBE_ (M_ * B_ * E_)
#define BNE_ (B_ * N_ * E_)

// ---------------------------------------------------------------------------
// Scratch (device globals; no allocations allowed)
// ---------------------------------------------------------------------------
__device__ float g_part[KS_ * MBE_];        // split-K partials of GFT
__device__ float g_xft[MBE_];               // y0[m][b][e]
__device__ float g_z1[MBE_];                // y0*W   [m][b][f]
__device__ float g_z2[MBE_];                // y0*W^2 [m][b][f]
__device__ float g_O[3 * BNE_];             // IGFT of the 3 fields [f][b][n][e]
__device__ __align__(16) __nv_bfloat16 g_Uhi[B_ * N_ * M_];     // [b][n][m]
__device__ __align__(16) __nv_bfloat16 g_Ulo[B_ * N_ * M_];
__device__ __align__(16) __nv_bfloat16 g_Uthi[B_ * M_ * N_];    // [b][m][i]
__device__ __align__(16) __nv_bfloat16 g_Utlo[B_ * M_ * N_];
__device__ __align__(16) __nv_bfloat16 g_xThi[B_ * E_ * N_];    // [b][e][i]
__device__ __align__(16) __nv_bfloat16 g_xTlo[B_ * E_ * N_];
__device__ __align__(16) __nv_bfloat16 g_Fhi[3 * B_ * E_ * M_]; // [f][b][e][m]
__device__ __align__(16) __nv_bfloat16 g_Flo[3 * B_ * E_ * M_];

// ---------------------------------------------------------------------------
// Base-arch PTX helpers (family target compute_103: no tcgen05, no cp.async)
// ---------------------------------------------------------------------------
__device__ __forceinline__ uint32_t smem_u32(const void* p) {
    uint32_t a;
    asm("{ .reg .u64 t; cvta.to.shared.u64 t, %1; cvt.u32.u64 %0, t; }" : "=r"(a) : "l"(p));
    return a;
}
#define LDSM4(r, addr) \
    asm volatile("ldmatrix.sync.aligned.m8n8.x4.shared.b16 {%0,%1,%2,%3}, [%4];" \
        : "=r"((r)[0]), "=r"((r)[1]), "=r"((r)[2]), "=r"((r)[3]) : "r"(addr))

#define MMA16816(c, a, b0, b1) \
    asm volatile("mma.sync.aligned.m16n8k16.row.col.f32.bf16.bf16.f32 " \
        "{%0,%1,%2,%3}, {%4,%5,%6,%7}, {%8,%9}, {%0,%1,%2,%3};" \
        : "+f"((c)[0]), "+f"((c)[1]), "+f"((c)[2]), "+f"((c)[3]) \
        : "r"((a)[0]), "r"((a)[1]), "r"((a)[2]), "r"((a)[3]), "r"(b0), "r"(b1))

__device__ __forceinline__ void pack_hilo(const float* f, uint2& hv, uint2& lv) {
    unsigned short hh[4], ll[4];
#pragma unroll
    for (int i = 0; i < 4; i++) {
        __nv_bfloat16 h = __float2bfloat16(f[i]);
        __nv_bfloat16 l = __float2bfloat16(f[i] - __bfloat162float(h));
        hh[i] = __bfloat16_as_ushort(h);
        ll[i] = __bfloat16_as_ushort(l);
    }
    hv = make_uint2((uint32_t)hh[0] | ((uint32_t)hh[1] << 16),
                    (uint32_t)hh[2] | ((uint32_t)hh[3] << 16));
    lv = make_uint2((uint32_t)ll[0] | ((uint32_t)ll[1] << 16),
                    (uint32_t)ll[2] | ((uint32_t)ll[3] << 16));
}

// ---------------------------------------------------------------------------
// K1: U conversions (one read of the U[:, :, :256] slice): g_Uhi/lo [b][n][m]
// AND g_Uthi/lo [b][m][i] (32x32 tile transpose).
// ---------------------------------------------------------------------------
__global__ __launch_bounds__(256) void k_convUX(const float* __restrict__ U) {
    __shared__ float tile[32][33];
    const int it = blockIdx.x & 31, mt = blockIdx.x >> 5;
    const int b = blockIdx.z;
    const int i0 = it * 32, m0 = mt * 32;
    const int r = threadIdx.x >> 3;
    const int cg = (threadIdx.x & 7) * 4;

    float4 v = *(const float4*)&U[((size_t)b * N_ + i0 + r) * N_ + m0 + cg];
    float f[4] = {v.x, v.y, v.z, v.w};
    uint2 hv, lv;
    pack_hilo(f, hv, lv);
    size_t o1 = ((size_t)b * N_ + i0 + r) * M_ + m0 + cg;
    *(uint2*)&g_Uhi[o1] = hv;
    *(uint2*)&g_Ulo[o1] = lv;

    tile[r][cg + 0] = v.x; tile[r][cg + 1] = v.y;
    tile[r][cg + 2] = v.z; tile[r][cg + 3] = v.w;
    __syncthreads();

    float ft[4];
#pragma unroll
    for (int k = 0; k < 4; k++) ft[k] = tile[cg + k][r];  // Ut[m0+r][i0+cg+k]
    pack_hilo(ft, hv, lv);
    size_t o2 = ((size_t)b * M_ + m0 + r) * N_ + i0 + cg;
    *(uint2*)&g_Uthi[o2] = hv;
    *(uint2*)&g_Utlo[o2] = lv;
}

// K1b: x[b][i][e] -> xT[b][e][i] bf16 hi/lo
__global__ __launch_bounds__(256) void k_convX(const float* __restrict__ x) {
    __shared__ float tile[32][33];
    const int it = blockIdx.x & 31, et = blockIdx.x >> 5;
    const int b = blockIdx.z;
    const int i0 = it * 32, e0 = et * 32;
    const int r = threadIdx.x >> 3;
    const int cg = (threadIdx.x & 7) * 4;

    float4 v = *(const float4*)&x[((size_t)b * N_ + i0 + r) * E_ + e0 + cg];
    tile[r][cg + 0] = v.x; tile[r][cg + 1] = v.y;
    tile[r][cg + 2] = v.z; tile[r][cg + 3] = v.w;
    __syncthreads();

    float ft[4];
#pragma unroll
    for (int k = 0; k < 4; k++) ft[k] = tile[cg + k][r];  // xT[e0+r][i0+cg+k]
    uint2 hv, lv;
    pack_hilo(ft, hv, lv);
    size_t o = ((size_t)b * E_ + e0 + r) * N_ + i0 + cg;
    *(uint2*)&g_xThi[o] = hv;
    *(uint2*)&g_xTlo[o] = lv;
}

// ---------------------------------------------------------------------------
// Shared MMA tile geometry
// ---------------------------------------------------------------------------
#define KC 64
#define STRIDE 72
#define BUF_ELT (128 * STRIDE)
#define BUF_B (BUF_ELT * 2)               // 18432 bytes
#define IG_SMEM (4 * BUF_B)               // 73728 bytes

// ---------------------------------------------------------------------------
// K2: GFT via mma.sync: part[ks][m][b][e] = sum_{i in slice} Ut[b][m][i]*xT[b][e][i]
// grid (2 mtile, 8 ks, 8 b); K=128 per CTA (2 chunks of 64).
// ---------------------------------------------------------------------------
__global__ __launch_bounds__(256, 2) void k_gft_mma() {
    extern __shared__ __nv_bfloat16 sm_bf[];
    const uint32_t sb = smem_u32(sm_bf);
    const int mt = blockIdx.x, ks = blockIdx.y, b = blockIdx.z;
    const int tid = threadIdx.x, wid = tid >> 5, lid = tid & 31;
    const int wm = wid >> 2, wn = wid & 3;
    const int kbase = ks * 128;

    const __nv_bfloat16* __restrict__ s0 = g_Uthi + ((size_t)b * M_ + mt * 128) * N_;
    const __nv_bfloat16* __restrict__ s1 = g_Utlo + ((size_t)b * M_ + mt * 128) * N_;
    const __nv_bfloat16* __restrict__ s2 = g_xThi + (size_t)b * E_ * N_;
    const __nv_bfloat16* __restrict__ s3 = g_xTlo + (size_t)b * E_ * N_;
    const __nv_bfloat16* srcs[4] = {s0, s1, s2, s3};

    float acc[4][4][4];
#pragma unroll
    for (int i = 0; i < 4; i++)
#pragma unroll
        for (int j = 0; j < 4; j++)
#pragma unroll
            for (int k = 0; k < 4; k++) acc[i][j][k] = 0.f;

    const uint32_t a_base = ((uint32_t)(wm * 64 + (lid & 15)) * STRIDE + (lid >> 4) * 8) * 2;
    const int btile = lid >> 3, brow = lid & 7;
    const uint32_t b_base = ((uint32_t)(wn * 32 + (btile >> 1) * 8 + brow) * STRIDE
                             + (btile & 1) * 8) * 2;
    const uint32_t Ah = sb, Al = sb + BUF_B, Bh = sb + 2 * BUF_B, Bl = sb + 3 * BUF_B;

    for (int c = 0; c < 2; c++) {
        if (c) __syncthreads();
#pragma unroll
        for (int bufi = 0; bufi < 4; bufi++) {
            const __nv_bfloat16* src = srcs[bufi] + kbase + c * KC;
            __nv_bfloat16* dstp = sm_bf + bufi * BUF_ELT;
#pragma unroll
            for (int i = 0; i < 4; i++) {
                int idx = tid + i * 256;
                int r = idx >> 3, q = (idx & 7) * 8;
                *(uint4*)(dstp + r * STRIDE + q) = *(const uint4*)(src + (size_t)r * N_ + q);
            }
        }
        __syncthreads();
#pragma unroll
        for (int ksm = 0; ksm < 4; ksm++) {
            uint32_t ah[4][4], al[4][4];
#pragma unroll
            for (int ma = 0; ma < 4; ma++) {
                uint32_t off = a_base + (uint32_t)(ma * 16 * STRIDE + ksm * 16) * 2;
                LDSM4(ah[ma], Ah + off);
                LDSM4(al[ma], Al + off);
            }
            uint32_t bh[2][4], bl[2][4];
#pragma unroll
            for (int p = 0; p < 2; p++) {
                uint32_t off = b_base + (uint32_t)(p * 16 * STRIDE + ksm * 16) * 2;
                LDSM4(bh[p], Bh + off);
                LDSM4(bl[p], Bl + off);
            }
#pragma unroll
            for (int ma = 0; ma < 4; ma++) {
#pragma unroll
                for (int p = 0; p < 2; p++) {
                    MMA16816(acc[ma][2 * p],     ah[ma], bh[p][0], bh[p][1]);
                    MMA16816(acc[ma][2 * p],     ah[ma], bl[p][0], bl[p][1]);
                    MMA16816(acc[ma][2 * p],     al[ma], bh[p][0], bh[p][1]);
                    MMA16816(acc[ma][2 * p + 1], ah[ma], bh[p][2], bh[p][3]);
                    MMA16816(acc[ma][2 * p + 1], ah[ma], bl[p][2], bl[p][3]);
                    MMA16816(acc[ma][2 * p + 1], al[ma], bh[p][2], bh[p][3]);
                }
            }
        }
    }

    // partial [ks][m][b][e]; consecutive m stride = B_*E_
    float* ob = g_part + (((size_t)ks * M_ + mt * 128) * B_ + b) * E_;
    const int r0 = lid >> 2, c0 = (lid & 3) * 2;
#pragma unroll
    for (int ma = 0; ma < 4; ma++) {
#pragma unroll
        for (int na = 0; na < 4; na++) {
            int row = wm * 64 + ma * 16 + r0;
            int col = wn * 32 + na * 8 + c0;
            *(float2*)&ob[(size_t)row * (B_ * E_) + col] =
                make_float2(acc[ma][na][0], acc[ma][na][1]);
            *(float2*)&ob[(size_t)(row + 8) * (B_ * E_) + col] =
                make_float2(acc[ma][na][2], acc[ma][na][3]);
        }
    }
}

// ---------------------------------------------------------------------------
// K3: per-mode: fused reduce (per-element ks-order identical) -> y0 ->
// z1 = y0*W -> z2 = z1*W.  W staged row-major in smem once per CTA.
// ---------------------------------------------------------------------------
#define KZ_SMEM ((128 * 128 + 2 * 8 * 128) * 4)   // 73728 bytes
__global__ __launch_bounds__(256, 2) void k_z(const float* __restrict__ W) {
    extern __shared__ float sm[];
    float* Ws = sm;                    // [128][128] row-major, 64KB
    float* ys = sm + 128 * 128;        // [b*128+e]
    float* zs = ys + 8 * 128;          // [b*128+f]
    const int m = blockIdx.x, tid = threadIdx.x;
    const int b = tid >> 5, fq = (tid & 31) * 4;
    const float* Wm = W + (size_t)m * E_ * E_;

#pragma unroll
    for (int i = 0; i < 16; i++) {
        int q = (tid + i * 256) * 4;
        *(float4*)&Ws[q] = *(const float4*)&Wm[q];
    }
    {
        int idx = tid * 4;
        const float* P = g_part + (size_t)m * B_ * E_ + idx;
        float4 s = make_float4(0.f, 0.f, 0.f, 0.f);
#pragma unroll
        for (int ks = 0; ks < KS_; ks++) {
            float4 v = *(const float4*)(P + (size_t)ks * MBE_);
            s.x += v.x; s.y += v.y; s.z += v.z; s.w += v.w;
        }
        *(float4*)&g_xft[(size_t)m * B_ * E_ + idx] = s;
        *(float4*)&ys[idx] = s;
    }
    __syncthreads();

    {
        float a0 = 0.f, a1 = 0.f, a2 = 0.f, a3 = 0.f;
        const float* Yb = &ys[b * 128];
#pragma unroll 8
        for (int e = 0; e < 128; e++) {
            float4 w = *(const float4*)&Ws[e * 128 + fq];
            float y = Yb[e];
            a0 += y * w.x; a1 += y * w.y; a2 += y * w.z; a3 += y * w.w;
        }
        *(float4*)&g_z1[((size_t)m * B_ + b) * E_ + fq] = make_float4(a0, a1, a2, a3);
        *(float4*)&zs[b * 128 + fq] = make_float4(a0, a1, a2, a3);
    }
    __syncthreads();

    {
        float a0 = 0.f, a1 = 0.f, a2 = 0.f, a3 = 0.f;
        const float* Zb = &zs[b * 128];
#pragma unroll 8
        for (int e = 0; e < 128; e++) {
            float4 w = *(const float4*)&Ws[e * 128 + fq];
            float y = Zb[e];
            a0 += y * w.x; a1 += y * w.y; a2 += y * w.z; a3 += y * w.w;
        }
        *(float4*)&g_z2[((size_t)m * B_ + b) * E_ + fq] = make_float4(a0, a1, a2, a3);
    }
}

// ---------------------------------------------------------------------------
// K4: transpose+convert field[m][b][e] -> [field][b][e][m] bf16 hi/lo
// ---------------------------------------------------------------------------
__global__ __launch_bounds__(256) void k_convF() {
    __shared__ float tile[32][33];
    const int mt = blockIdx.x & 7, et = blockIdx.x >> 3;
    const int fld = blockIdx.y, b = blockIdx.z;
    const int m0 = mt * 32, e0 = et * 32;
    const int r = threadIdx.x >> 3;
    const int cg = (threadIdx.x & 7) * 4;

    const float* F = (fld == 0) ? g_xft : (fld == 1) ? g_z1 : g_z2;
    float4 v = *(const float4*)&F[(((size_t)(m0 + r)) * B_ + b) * E_ + e0 + cg];
    tile[r][cg + 0] = v.x; tile[r][cg + 1] = v.y;
    tile[r][cg + 2] = v.z; tile[r][cg + 3] = v.w;
    __syncthreads();

    float ft[4];
#pragma unroll
    for (int i = 0; i < 4; i++) ft[i] = tile[cg + i][r];
    uint2 hv, lv;
    pack_hilo(ft, hv, lv);
    size_t o = (((size_t)fld * B_ + b) * E_ + e0 + r) * M_ + m0 + cg;
    *(uint2*)&g_Fhi[o] = hv;
    *(uint2*)&g_Flo[o] = lv;
}

// ---------------------------------------------------------------------------
// K5: IGFT of the 3 fields via warp-level bf16 mma.sync.
// fld 0 (y0): hi/lo split, 3 MMAs per product (full precision).
// fld 1,2 (z1 ~4e-3, z2 ~1.5e-5 of y0): single bf16 MMA — their output
// contribution is scaled down by the field magnitude, so bf16 error (~4e-3
// rel of the field) contributes only ~1.6e-5 rel to the final output.
// ---------------------------------------------------------------------------
__global__ __launch_bounds__(256, 2) void k_igft_mma() {
    extern __shared__ __nv_bfloat16 sm_bf[];
    const uint32_t sb = smem_u32(sm_bf);
    const int nt = blockIdx.x, fld = blockIdx.y, b = blockIdx.z;
    const int tid = threadIdx.x, wid = tid >> 5, lid = tid & 31;
    const int n0 = nt * 128;
    const int wm = wid >> 2, wn = wid & 3;
    const bool heavy = (fld == 0);

    const __nv_bfloat16* __restrict__ s0 = g_Uhi + ((size_t)b * N_ + n0) * M_;
    const __nv_bfloat16* __restrict__ s1 = g_Ulo + ((size_t)b * N_ + n0) * M_;
    const __nv_bfloat16* __restrict__ s2 = g_Fhi + ((size_t)fld * B_ + b) * E_ * M_;
    const __nv_bfloat16* __restrict__ s3 = g_Flo + ((size_t)fld * B_ + b) * E_ * M_;
    const __nv_bfloat16* srcs[4] = {s0, s1, s2, s3};

    float acc[4][4][4];
#pragma unroll
    for (int i = 0; i < 4; i++)
#pragma unroll
        for (int j = 0; j < 4; j++)
#pragma unroll
            for (int k = 0; k < 4; k++) acc[i][j][k] = 0.f;

    const uint32_t a_base = ((uint32_t)(wm * 64 + (lid & 15)) * STRIDE + (lid >> 4) * 8) * 2;
    const int btile = lid >> 3, brow = lid & 7;
    const uint32_t b_base = ((uint32_t)(wn * 32 + (btile >> 1) * 8 + brow) * STRIDE
                             + (btile & 1) * 8) * 2;
    const uint32_t Ah = sb, Al = sb + BUF_B, Bh = sb + 2 * BUF_B, Bl = sb + 3 * BUF_B;

    for (int c = 0; c < 4; c++) {
        if (c) __syncthreads();
#pragma unroll
        for (int bufi = 0; bufi < 4; bufi++) {
            if (!heavy && (bufi == 1 || bufi == 3)) continue;  // lo not needed
            const __nv_bfloat16* src = srcs[bufi] + c * KC;
            __nv_bfloat16* dstp = sm_bf + bufi * BUF_ELT;
#pragma unroll
            for (int i = 0; i < 4; i++) {
                int idx = tid + i * 256;
                int r = idx >> 3, q = (idx & 7) * 8;
                *(uint4*)(dstp + r * STRIDE + q) = *(const uint4*)(src + (size_t)r * M_ + q);
            }
        }
        __syncthreads();
#pragma unroll
        for (int ks = 0; ks < 4; ks++) {
            uint32_t ah[4][4], al[4][4];
#pragma unroll
            for (int ma = 0; ma < 4; ma++) {
                uint32_t off = a_base + (uint32_t)(ma * 16 * STRIDE + ks * 16) * 2;
                LDSM4(ah[ma], Ah + off);
                if (heavy) LDSM4(al[ma], Al + off);
            }
            uint32_t bh[2][4], bl[2][4];
#pragma unroll
            for (int p = 0; p < 2; p++) {
                uint32_t off = b_base + (uint32_t)(p * 16 * STRIDE + ks * 16) * 2;
                LDSM4(bh[p], Bh + off);
                if (heavy) LDSM4(bl[p], Bl + off);
            }
#pragma unroll
            for (int ma = 0; ma < 4; ma++) {
#pragma unroll
                for (int p = 0; p < 2; p++) {
                    MMA16816(acc[ma][2 * p],     ah[ma], bh[p][0], bh[p][1]);
                    MMA16816(acc[ma][2 * p + 1], ah[ma], bh[p][2], bh[p][3]);
                    if (heavy) {
                        MMA16816(acc[ma][2 * p],     ah[ma], bl[p][0], bl[p][1]);
                        MMA16816(acc[ma][2 * p],     al[ma], bh[p][0], bh[p][1]);
                        MMA16816(acc[ma][2 * p + 1], ah[ma], bl[p][2], bl[p][3]);
                        MMA16816(acc[ma][2 * p + 1], al[ma], bh[p][2], bh[p][3]);
                    }
                }
            }
        }
    }

    float* ob = g_O + (((size_t)fld * B_ + b) * N_ + n0) * E_;
    const int r0 = lid >> 2, c0 = (lid & 3) * 2;
#pragma unroll
    for (int ma = 0; ma < 4; ma++) {
#pragma unroll
        for (int na = 0; na < 4; na++) {
            int row = wm * 64 + ma * 16 + r0;
            int col = wn * 32 + na * 8 + c0;
            *(float2*)&ob[(size_t)row * E_ + col] =
                make_float2(acc[ma][na][0], acc[ma][na][1]);
            *(float2*)&ob[(size_t)(row + 8) * E_ + col] =
                make_float2(acc[ma][na][2], acc[ma][na][3]);
        }
    }
}

// ---------------------------------------------------------------------------
// K6: combine (r-major, t-inner: O read once).
// out[t][r] = O0[r] + c1(t)*O1[r] + c2(t)*O2[r],  c1(t)=times[t], c2=c1^2/2
// ---------------------------------------------------------------------------
__global__ __launch_bounds__(256) void k_combine(const float* __restrict__ times,
                                                 float* __restrict__ out) {
    int idx4 = (blockIdx.x * 256 + threadIdx.x) * 4;   // < BNE_
    float4 o0 = *(const float4*)&g_O[idx4];
    float4 o1 = *(const float4*)&g_O[BNE_ + idx4];
    float4 o2 = *(const float4*)&g_O[2 * BNE_ + idx4];
#pragma unroll
    for (int t = 0; t < T_; t++) {
        float c1 = __ldg(&times[t]);
        float c2 = 0.5f * c1 * c1;
        float4 v;
        v.x = o0.x + c1 * o1.x + c2 * o2.x;
        v.y = o0.y + c1 * o1.y + c2 * o2.y;
        v.z = o0.z + c1 * o1.z + c2 * o2.z;
        v.w = o0.w + c1 * o1.w + c2 * o2.w;
        *(float4*)&out[(size_t)t * BNE_ + idx4] = v;
    }
}

// ---------------------------------------------------------------------------
extern "C" void kernel_launch(void* const* d_in, const int* in_sizes, int n_in,
                              void* d_out, int out_size) {
    const float* x     = (const float*)d_in[0];   // [B,N,E]
    const float* times = (const float*)d_in[1];   // [B,T]
    const float* U     = (const float*)d_in[2];   // [B,N,N]
    const float* W     = (const float*)d_in[3];   // [M,E,E]
    float* out = (float*)d_out;                   // [T,B,N,E]

    cudaFuncSetAttribute(k_gft_mma,  cudaFuncAttributeMaxDynamicSharedMemorySize, IG_SMEM);
    cudaFuncSetAttribute(k_z,        cudaFuncAttributeMaxDynamicSharedMemorySize, KZ_SMEM);
    cudaFuncSetAttribute(k_igft_mma, cudaFuncAttributeMaxDynamicSharedMemorySize, IG_SMEM);

    k_convUX<<<dim3(256, 1, B_), 256>>>(U);
    k_convX<<<dim3(128, 1, B_), 256>>>(x);
    k_gft_mma<<<dim3(2, KS_, B_), 256, IG_SMEM>>>();
    k_z<<<M_, 256, KZ_SMEM>>>(W);
    k_convF<<<dim3(32, 3, B_), 256>>>();
    k_igft_mma<<<dim3(N_ / 128, 3, B_), 256, IG_SMEM>>>();
    k_combine<<<BNE_ / 1024, 256>>>(times, out);
}

// round 15
// speedup vs baseline: 1.0058x; 1.0058x over previous
#include <cuda_runtime.h>
#include <cuda_bf16.h>
#include <cstdint>

#define B_ 8
#define N_ 1024
#define E_ 128
#define T_ 16
#define M_ 256
#define KS_ 8
#define MBE_ (M_ * B_ * E_)
#define BNE_ (B_ * N_ * E_)

// ---------------------------------------------------------------------------
// Scratch (device globals; no allocations allowed)
// ---------------------------------------------------------------------------
__device__ float g_part[KS_ * MBE_];        // split-K partials of GFT
__device__ float g_xft[MBE_];               // y0[m][b][e]
__device__ float g_z1[MBE_];                // y0*W   [m][b][f]
__device__ float g_z2[MBE_];                // y0*W^2 [m][b][f]
__device__ float g_O[3 * BNE_];             // IGFT of the 3 fields [f][b][n][e]
__device__ __align__(16) __nv_bfloat16 g_Uhi[B_ * N_ * M_];     // [b][n][m]
__device__ __align__(16) __nv_bfloat16 g_Ulo[B_ * N_ * M_];
__device__ __align__(16) __nv_bfloat16 g_Uthi[B_ * M_ * N_];    // [b][m][i]
__device__ __align__(16) __nv_bfloat16 g_Utlo[B_ * M_ * N_];
__device__ __align__(16) __nv_bfloat16 g_xThi[B_ * E_ * N_];    // [b][e][i]
__device__ __align__(16) __nv_bfloat16 g_xTlo[B_ * E_ * N_];
__device__ __align__(16) __nv_bfloat16 g_Fhi[3 * B_ * E_ * M_]; // [f][b][e][m]
__device__ __align__(16) __nv_bfloat16 g_Flo[3 * B_ * E_ * M_];

// ---------------------------------------------------------------------------
// Base-arch PTX helpers (family target compute_103: no tcgen05)
// ---------------------------------------------------------------------------
__device__ __forceinline__ uint32_t smem_u32(const void* p) {
    uint32_t a;
    asm("{ .reg .u64 t; cvta.to.shared.u64 t, %1; cvt.u32.u64 %0, t; }" : "=r"(a) : "l"(p));
    return a;
}
#define LDSM4(r, addr) \
    asm volatile("ldmatrix.sync.aligned.m8n8.x4.shared.b16 {%0,%1,%2,%3}, [%4];" \
        : "=r"((r)[0]), "=r"((r)[1]), "=r"((r)[2]), "=r"((r)[3]) : "r"(addr))

#define MMA16816(c, a, b0, b1) \
    asm volatile("mma.sync.aligned.m16n8k16.row.col.f32.bf16.bf16.f32 " \
        "{%0,%1,%2,%3}, {%4,%5,%6,%7}, {%8,%9}, {%0,%1,%2,%3};" \
        : "+f"((c)[0]), "+f"((c)[1]), "+f"((c)[2]), "+f"((c)[3]) \
        : "r"((a)[0]), "r"((a)[1]), "r"((a)[2]), "r"((a)[3]), "r"(b0), "r"(b1))

__device__ __forceinline__ void pack_hilo(const float* f, uint2& hv, uint2& lv) {
    unsigned short hh[4], ll[4];
#pragma unroll
    for (int i = 0; i < 4; i++) {
        __nv_bfloat16 h = __float2bfloat16(f[i]);
        __nv_bfloat16 l = __float2bfloat16(f[i] - __bfloat162float(h));
        hh[i] = __bfloat16_as_ushort(h);
        ll[i] = __bfloat16_as_ushort(l);
    }
    hv = make_uint2((uint32_t)hh[0] | ((uint32_t)hh[1] << 16),
                    (uint32_t)hh[2] | ((uint32_t)hh[3] << 16));
    lv = make_uint2((uint32_t)ll[0] | ((uint32_t)ll[1] << 16),
                    (uint32_t)ll[2] | ((uint32_t)ll[3] << 16));
}

// ---------------------------------------------------------------------------
// K1: U conversions (one read of the U[:, :, :256] slice): g_Uhi/lo [b][n][m]
// AND g_Uthi/lo [b][m][i] (32x32 tile transpose).
// ---------------------------------------------------------------------------
__global__ __launch_bounds__(256) void k_convUX(const float* __restrict__ U) {
    __shared__ float tile[32][33];
    const int it = blockIdx.x & 31, mt = blockIdx.x >> 5;
    const int b = blockIdx.z;
    const int i0 = it * 32, m0 = mt * 32;
    const int r = threadIdx.x >> 3;
    const int cg = (threadIdx.x & 7) * 4;

    float4 v = *(const float4*)&U[((size_t)b * N_ + i0 + r) * N_ + m0 + cg];
    float f[4] = {v.x, v.y, v.z, v.w};
    uint2 hv, lv;
    pack_hilo(f, hv, lv);
    size_t o1 = ((size_t)b * N_ + i0 + r) * M_ + m0 + cg;
    *(uint2*)&g_Uhi[o1] = hv;
    *(uint2*)&g_Ulo[o1] = lv;

    tile[r][cg + 0] = v.x; tile[r][cg + 1] = v.y;
    tile[r][cg + 2] = v.z; tile[r][cg + 3] = v.w;
    __syncthreads();

    float ft[4];
#pragma unroll
    for (int k = 0; k < 4; k++) ft[k] = tile[cg + k][r];  // Ut[m0+r][i0+cg+k]
    pack_hilo(ft, hv, lv);
    size_t o2 = ((size_t)b * M_ + m0 + r) * N_ + i0 + cg;
    *(uint2*)&g_Uthi[o2] = hv;
    *(uint2*)&g_Utlo[o2] = lv;
}

// K1b: x[b][i][e] -> xT[b][e][i] bf16 hi/lo
__global__ __launch_bounds__(256) void k_convX(const float* __restrict__ x) {
    __shared__ float tile[32][33];
    const int it = blockIdx.x & 31, et = blockIdx.x >> 5;
    const int b = blockIdx.z;
    const int i0 = it * 32, e0 = et * 32;
    const int r = threadIdx.x >> 3;
    const int cg = (threadIdx.x & 7) * 4;

    float4 v = *(const float4*)&x[((size_t)b * N_ + i0 + r) * E_ + e0 + cg];
    tile[r][cg + 0] = v.x; tile[r][cg + 1] = v.y;
    tile[r][cg + 2] = v.z; tile[r][cg + 3] = v.w;
    __syncthreads();

    float ft[4];
#pragma unroll
    for (int k = 0; k < 4; k++) ft[k] = tile[cg + k][r];  // xT[e0+r][i0+cg+k]
    uint2 hv, lv;
    pack_hilo(ft, hv, lv);
    size_t o = ((size_t)b * E_ + e0 + r) * N_ + i0 + cg;
    *(uint2*)&g_xThi[o] = hv;
    *(uint2*)&g_xTlo[o] = lv;
}

// ---------------------------------------------------------------------------
// Shared MMA tile geometry
// ---------------------------------------------------------------------------
#define KC 64
#define STRIDE 72
#define BUF_ELT (128 * STRIDE)
#define BUF_B (BUF_ELT * 2)               // 18432 bytes
#define IG_SMEM (4 * BUF_B)               // 73728 bytes

// ---------------------------------------------------------------------------
// K2: GFT via mma.sync: part[ks][m][b][e] = sum_{i in slice} Ut[b][m][i]*xT[b][e][i]
// grid (2 mtile, 8 ks, 8 b); K=128 per CTA (2 chunks of 64).
// ---------------------------------------------------------------------------
__global__ __launch_bounds__(256, 2) void k_gft_mma() {
    extern __shared__ __nv_bfloat16 sm_bf[];
    const uint32_t sb = smem_u32(sm_bf);
    const int mt = blockIdx.x, ks = blockIdx.y, b = blockIdx.z;
    const int tid = threadIdx.x, wid = tid >> 5, lid = tid & 31;
    const int wm = wid >> 2, wn = wid & 3;
    const int kbase = ks * 128;

    const __nv_bfloat16* __restrict__ s0 = g_Uthi + ((size_t)b * M_ + mt * 128) * N_;
    const __nv_bfloat16* __restrict__ s1 = g_Utlo + ((size_t)b * M_ + mt * 128) * N_;
    const __nv_bfloat16* __restrict__ s2 = g_xThi + (size_t)b * E_ * N_;
    const __nv_bfloat16* __restrict__ s3 = g_xTlo + (size_t)b * E_ * N_;
    const __nv_bfloat16* srcs[4] = {s0, s1, s2, s3};

    float acc[4][4][4];
#pragma unroll
    for (int i = 0; i < 4; i++)
#pragma unroll
        for (int j = 0; j < 4; j++)
#pragma unroll
            for (int k = 0; k < 4; k++) acc[i][j][k] = 0.f;

    const uint32_t a_base = ((uint32_t)(wm * 64 + (lid & 15)) * STRIDE + (lid >> 4) * 8) * 2;
    const int btile = lid >> 3, brow = lid & 7;
    const uint32_t b_base = ((uint32_t)(wn * 32 + (btile >> 1) * 8 + brow) * STRIDE
                             + (btile & 1) * 8) * 2;
    const uint32_t Ah = sb, Al = sb + BUF_B, Bh = sb + 2 * BUF_B, Bl = sb + 3 * BUF_B;

    for (int c = 0; c < 2; c++) {
        if (c) __syncthreads();
#pragma unroll
        for (int bufi = 0; bufi < 4; bufi++) {
            const __nv_bfloat16* src = srcs[bufi] + kbase + c * KC;
            __nv_bfloat16* dstp = sm_bf + bufi * BUF_ELT;
#pragma unroll
            for (int i = 0; i < 4; i++) {
                int idx = tid + i * 256;
                int r = idx >> 3, q = (idx & 7) * 8;
                *(uint4*)(dstp + r * STRIDE + q) = *(const uint4*)(src + (size_t)r * N_ + q);
            }
        }
        __syncthreads();
#pragma unroll
        for (int ksm = 0; ksm < 4; ksm++) {
            uint32_t ah[4][4], al[4][4];
#pragma unroll
            for (int ma = 0; ma < 4; ma++) {
                uint32_t off = a_base + (uint32_t)(ma * 16 * STRIDE + ksm * 16) * 2;
                LDSM4(ah[ma], Ah + off);
                LDSM4(al[ma], Al + off);
            }
            uint32_t bh[2][4], bl[2][4];
#pragma unroll
            for (int p = 0; p < 2; p++) {
                uint32_t off = b_base + (uint32_t)(p * 16 * STRIDE + ksm * 16) * 2;
                LDSM4(bh[p], Bh + off);
                LDSM4(bl[p], Bl + off);
            }
#pragma unroll
            for (int ma = 0; ma < 4; ma++) {
#pragma unroll
                for (int p = 0; p < 2; p++) {
                    MMA16816(acc[ma][2 * p],     ah[ma], bh[p][0], bh[p][1]);
                    MMA16816(acc[ma][2 * p],     ah[ma], bl[p][0], bl[p][1]);
                    MMA16816(acc[ma][2 * p],     al[ma], bh[p][0], bh[p][1]);
                    MMA16816(acc[ma][2 * p + 1], ah[ma], bh[p][2], bh[p][3]);
                    MMA16816(acc[ma][2 * p + 1], ah[ma], bl[p][2], bl[p][3]);
                    MMA16816(acc[ma][2 * p + 1], al[ma], bh[p][2], bh[p][3]);
                }
            }
        }
    }

    // partial [ks][m][b][e]; consecutive m stride = B_*E_
    float* ob = g_part + (((size_t)ks * M_ + mt * 128) * B_ + b) * E_;
    const int r0 = lid >> 2, c0 = (lid & 3) * 2;
#pragma unroll
    for (int ma = 0; ma < 4; ma++) {
#pragma unroll
        for (int na = 0; na < 4; na++) {
            int row = wm * 64 + ma * 16 + r0;
            int col = wn * 32 + na * 8 + c0;
            *(float2*)&ob[(size_t)row * (B_ * E_) + col] =
                make_float2(acc[ma][na][0], acc[ma][na][1]);
            *(float2*)&ob[(size_t)(row + 8) * (B_ * E_) + col] =
                make_float2(acc[ma][na][2], acc[ma][na][3]);
        }
    }
}

// ---------------------------------------------------------------------------
// K3: per-mode: fused reduce (per-element ks-order identical) -> y0 ->
// z1 = y0*W -> z2 = z1*W.
// W staged in smem as BF16 (32KB instead of 64KB): 4 CTAs/SM instead of 2
// doubles stage-latency overlap; LDS wavefronts in the passes halve.
// bf16-W error adds ~1.6e-5 rel to the output (z1's weight is ~4e-3 of y0).
// ---------------------------------------------------------------------------
#define KZ_SMEM (128 * 128 * 2 + 2 * 8 * 128 * 4)   // 32768 + 8192 = 40960
__global__ __launch_bounds__(256, 4) void k_z(const float* __restrict__ W) {
    extern __shared__ char smc[];
    __nv_bfloat16* Ws = (__nv_bfloat16*)smc;        // [128*128] bf16, 32KB
    float* ys = (float*)(smc + 128 * 128 * 2);      // [b*128+e]
    float* zs = ys + 8 * 128;                       // [b*128+f]
    const int m = blockIdx.x, tid = threadIdx.x;
    const int b = tid >> 5, fq = (tid & 31) * 4;
    const float* Wm = W + (size_t)m * E_ * E_;

    // stage W fp32->bf16: 16384 elems, 16 float4 per thread
#pragma unroll 4
    for (int i = 0; i < 16; i++) {
        int q = (tid + i * 256) * 4;
        float4 v = *(const float4*)&Wm[q];
        unsigned short w0 = __bfloat16_as_ushort(__float2bfloat16(v.x));
        unsigned short w1 = __bfloat16_as_ushort(__float2bfloat16(v.y));
        unsigned short w2 = __bfloat16_as_ushort(__float2bfloat16(v.z));
        unsigned short w3 = __bfloat16_as_ushort(__float2bfloat16(v.w));
        uint2 p = make_uint2((uint32_t)w0 | ((uint32_t)w1 << 16),
                             (uint32_t)w2 | ((uint32_t)w3 << 16));
        *(uint2*)&Ws[q] = p;
    }
    // fused reduction: y0 = sum_ks part[ks][m] (per-element order unchanged)
    {
        int idx = tid * 4;
        const float* P = g_part + (size_t)m * B_ * E_ + idx;
        float4 s = make_float4(0.f, 0.f, 0.f, 0.f);
#pragma unroll
        for (int ks = 0; ks < KS_; ks++) {
            float4 v = *(const float4*)(P + (size_t)ks * MBE_);
            s.x += v.x; s.y += v.y; s.z += v.z; s.w += v.w;
        }
        *(float4*)&g_xft[(size_t)m * B_ * E_ + idx] = s;
        *(float4*)&ys[idx] = s;
    }
    __syncthreads();

    // pass 1: z1[b][fq..fq+3] = sum_e y0[b][e] * W[e][fq..fq+3]
    {
        float a0 = 0.f, a1 = 0.f, a2 = 0.f, a3 = 0.f;
        const float* Yb = &ys[b * 128];
#pragma unroll 8
        for (int e = 0; e < 128; e++) {
            uint2 wp = *(const uint2*)&Ws[e * 128 + fq];
            float2 fa = __bfloat1622float2(*reinterpret_cast<__nv_bfloat162*>(&wp.x));
            float2 fb = __bfloat1622float2(*reinterpret_cast<__nv_bfloat162*>(&wp.y));
            float y = Yb[e];
            a0 += y * fa.x; a1 += y * fa.y; a2 += y * fb.x; a3 += y * fb.y;
        }
        *(float4*)&g_z1[((size_t)m * B_ + b) * E_ + fq] = make_float4(a0, a1, a2, a3);
        *(float4*)&zs[b * 128 + fq] = make_float4(a0, a1, a2, a3);
    }
    __syncthreads();

    // pass 2: z2[b][g..g+3] = sum_f z1[b][f] * W[f][g..g+3]
    {
        float a0 = 0.f, a1 = 0.f, a2 = 0.f, a3 = 0.f;
        const float* Zb = &zs[b * 128];
#pragma unroll 8
        for (int e = 0; e < 128; e++) {
            uint2 wp = *(const uint2*)&Ws[e * 128 + fq];
            float2 fa = __bfloat1622float2(*reinterpret_cast<__nv_bfloat162*>(&wp.x));
            float2 fb = __bfloat1622float2(*reinterpret_cast<__nv_bfloat162*>(&wp.y));
            float y = Zb[e];
            a0 += y * fa.x; a1 += y * fa.y; a2 += y * fb.x; a3 += y * fb.y;
        }
        *(float4*)&g_z2[((size_t)m * B_ + b) * E_ + fq] = make_float4(a0, a1, a2, a3);
    }
}

// ---------------------------------------------------------------------------
// K4: transpose+convert field[m][b][e] -> [field][b][e][m] bf16 hi/lo
// ---------------------------------------------------------------------------
__global__ __launch_bounds__(256) void k_convF() {
    __shared__ float tile[32][33];
    const int mt = blockIdx.x & 7, et = blockIdx.x >> 3;
    const int fld = blockIdx.y, b = blockIdx.z;
    const int m0 = mt * 32, e0 = et * 32;
    const int r = threadIdx.x >> 3;
    const int cg = (threadIdx.x & 7) * 4;

    const float* F = (fld == 0) ? g_xft : (fld == 1) ? g_z1 : g_z2;
    float4 v = *(const float4*)&F[(((size_t)(m0 + r)) * B_ + b) * E_ + e0 + cg];
    tile[r][cg + 0] = v.x; tile[r][cg + 1] = v.y;
    tile[r][cg + 2] = v.z; tile[r][cg + 3] = v.w;
    __syncthreads();

    float ft[4];
#pragma unroll
    for (int i = 0; i < 4; i++) ft[i] = tile[cg + i][r];
    uint2 hv, lv;
    pack_hilo(ft, hv, lv);
    size_t o = (((size_t)fld * B_ + b) * E_ + e0 + r) * M_ + m0 + cg;
    *(uint2*)&g_Fhi[o] = hv;
    *(uint2*)&g_Flo[o] = lv;
}

// ---------------------------------------------------------------------------
// K5: IGFT of the 3 fields via warp-level bf16 mma.sync.
// fld 0 (y0): hi/lo split, 3 MMAs per product.  fld 1,2: single bf16 MMA
// (their output weight is ~4e-3 / ~1.5e-5 of y0).
// ---------------------------------------------------------------------------
__global__ __launch_bounds__(256, 2) void k_igft_mma() {
    extern __shared__ __nv_bfloat16 sm_bf[];
    const uint32_t sb = smem_u32(sm_bf);
    const int nt = blockIdx.x, fld = blockIdx.y, b = blockIdx.z;
    const int tid = threadIdx.x, wid = tid >> 5, lid = tid & 31;
    const int n0 = nt * 128;
    const int wm = wid >> 2, wn = wid & 3;
    const bool heavy = (fld == 0);

    const __nv_bfloat16* __restrict__ s0 = g_Uhi + ((size_t)b * N_ + n0) * M_;
    const __nv_bfloat16* __restrict__ s1 = g_Ulo + ((size_t)b * N_ + n0) * M_;
    const __nv_bfloat16* __restrict__ s2 = g_Fhi + ((size_t)fld * B_ + b) * E_ * M_;
    const __nv_bfloat16* __restrict__ s3 = g_Flo + ((size_t)fld * B_ + b) * E_ * M_;
    const __nv_bfloat16* srcs[4] = {s0, s1, s2, s3};

    float acc[4][4][4];
#pragma unroll
    for (int i = 0; i < 4; i++)
#pragma unroll
        for (int j = 0; j < 4; j++)
#pragma unroll
            for (int k = 0; k < 4; k++) acc[i][j][k] = 0.f;

    const uint32_t a_base = ((uint32_t)(wm * 64 + (lid & 15)) * STRIDE + (lid >> 4) * 8) * 2;
    const int btile = lid >> 3, brow = lid & 7;
    const uint32_t b_base = ((uint32_t)(wn * 32 + (btile >> 1) * 8 + brow) * STRIDE
                             + (btile & 1) * 8) * 2;
    const uint32_t Ah = sb, Al = sb + BUF_B, Bh = sb + 2 * BUF_B, Bl = sb + 3 * BUF_B;

    for (int c = 0; c < 4; c++) {
        if (c) __syncthreads();
#pragma unroll
        for (int bufi = 0; bufi < 4; bufi++) {
            if (!heavy && (bufi == 1 || bufi == 3)) continue;  // lo not needed
            const __nv_bfloat16* src = srcs[bufi] + c * KC;
            __nv_bfloat16* dstp = sm_bf + bufi * BUF_ELT;
#pragma unroll
            for (int i = 0; i < 4; i++) {
                int idx = tid + i * 256;
                int r = idx >> 3, q = (idx & 7) * 8;
                *(uint4*)(dstp + r * STRIDE + q) = *(const uint4*)(src + (size_t)r * M_ + q);
            }
        }
        __syncthreads();
#pragma unroll
        for (int ks = 0; ks < 4; ks++) {
            uint32_t ah[4][4], al[4][4];
#pragma unroll
            for (int ma = 0; ma < 4; ma++) {
                uint32_t off = a_base + (uint32_t)(ma * 16 * STRIDE + ks * 16) * 2;
                LDSM4(ah[ma], Ah + off);
                if (heavy) LDSM4(al[ma], Al + off);
            }
            uint32_t bh[2][4], bl[2][4];
#pragma unroll
            for (int p = 0; p < 2; p++) {
                uint32_t off = b_base + (uint32_t)(p * 16 * STRIDE + ks * 16) * 2;
                LDSM4(bh[p], Bh + off);
                if (heavy) LDSM4(bl[p], Bl + off);
            }
#pragma unroll
            for (int ma = 0; ma < 4; ma++) {
#pragma unroll
                for (int p = 0; p < 2; p++) {
                    MMA16816(acc[ma][2 * p],     ah[ma], bh[p][0], bh[p][1]);
                    MMA16816(acc[ma][2 * p + 1], ah[ma], bh[p][2], bh[p][3]);
                    if (heavy) {
                        MMA16816(acc[ma][2 * p],     ah[ma], bl[p][0], bl[p][1]);
                        MMA16816(acc[ma][2 * p],     al[ma], bh[p][0], bh[p][1]);
                        MMA16816(acc[ma][2 * p + 1], ah[ma], bl[p][2], bl[p][3]);
                        MMA16816(acc[ma][2 * p + 1], al[ma], bh[p][2], bh[p][3]);
                    }
                }
            }
        }
    }

    float* ob = g_O + (((size_t)fld * B_ + b) * N_ + n0) * E_;
    const int r0 = lid >> 2, c0 = (lid & 3) * 2;
#pragma unroll
    for (int ma = 0; ma < 4; ma++) {
#pragma unroll
        for (int na = 0; na < 4; na++) {
            int row = wm * 64 + ma * 16 + r0;
            int col = wn * 32 + na * 8 + c0;
            *(float2*)&ob[(size_t)row * E_ + col] =
                make_float2(acc[ma][na][0], acc[ma][na][1]);
            *(float2*)&ob[(size_t)(row + 8) * E_ + col] =
                make_float2(acc[ma][na][2], acc[ma][na][3]);
        }
    }
}

// ---------------------------------------------------------------------------
// K6: combine (r-major, t-inner: O read once).
// out[t][r] = O0[r] + c1(t)*O1[r] + c2(t)*O2[r],  c1(t)=times[t], c2=c1^2/2
// ---------------------------------------------------------------------------
__global__ __launch_bounds__(256) void k_combine(const float* __restrict__ times,
                                                 float* __restrict__ out) {
    int idx4 = (blockIdx.x * 256 + threadIdx.x) * 4;   // < BNE_
    float4 o0 = *(const float4*)&g_O[idx4];
    float4 o1 = *(const float4*)&g_O[BNE_ + idx4];
    float4 o2 = *(const float4*)&g_O[2 * BNE_ + idx4];
#pragma unroll
    for (int t = 0; t < T_; t++) {
        float c1 = __ldg(&times[t]);
        float c2 = 0.5f * c1 * c1;
        float4 v;
        v.x = o0.x + c1 * o1.x + c2 * o2.x;
        v.y = o0.y + c1 * o1.y + c2 * o2.y;
        v.z = o0.z + c1 * o1.z + c2 * o2.z;
        v.w = o0.w + c1 * o1.w + c2 * o2.w;
        *(float4*)&out[(size_t)t * BNE_ + idx4] = v;
    }
}

// ---------------------------------------------------------------------------
extern "C" void kernel_launch(void* const* d_in, const int* in_sizes, int n_in,
                              void* d_out, int out_size) {
    const float* x     = (const float*)d_in[0];   // [B,N,E]
    const float* times = (const float*)d_in[1];   // [B,T]
    const float* U     = (const float*)d_in[2];   // [B,N,N]
    const float* W     = (const float*)d_in[3];   // [M,E,E]
    float* out = (float*)d_out;                   // [T,B,N,E]

    cudaFuncSetAttribute(k_gft_mma,  cudaFuncAttributeMaxDynamicSharedMemorySize, IG_SMEM);
    cudaFuncSetAttribute(k_z,        cudaFuncAttributeMaxDynamicSharedMemorySize, KZ_SMEM);
    cudaFuncSetAttribute(k_igft_mma, cudaFuncAttributeMaxDynamicSharedMemorySize, IG_SMEM);

    k_convUX<<<dim3(256, 1, B_), 256>>>(U);
    k_convX<<<dim3(128, 1, B_), 256>>>(x);
    k_gft_mma<<<dim3(2, KS_, B_), 256, IG_SMEM>>>();
    k_z<<<M_, 256, KZ_SMEM>>>(W);
    k_convF<<<dim3(32, 3, B_), 256>>>();
    k_igft_mma<<<dim3(N_ / 128, 3, B_), 256, IG_SMEM>>>();
    k_combine<<<BNE_ / 1024, 256>>>(times, out);
}